// round 8
// baseline (speedup 1.0000x reference)
#include <cuda_runtime.h>
#include <cstdint>

// SpatialCorrelationSampler via warp-level mma.sync bf16 (hi/lo split, fp32 acc).
// Round 8: 8x8 pixel tile (minimizes halo-GEMM overhead: N=256 vs 384),
// 2 blocks/SM (regs<=128, smem 67.6KB) for 16 warps/SM latency hiding.
//
// Per block: M=64 px, N=256 halo px (16x16), K=256.
// D[p][q] = sum_k A[p][k]*B[q][k];  outputs = band q=(hp+dy)*16+(wp+dx).

namespace {

constexpr int C = 256, H = 128, W = 128, PATCH = 9, PAD = 4;
constexpr int HW = H * W;
constexpr int TW = 8, TH = 8;
constexpr int CCH = 32, NCHUNK = C / CCH;          // 8

constexpr int A_STRIDE = 144;                      // 64 px * 2B + 16 pad
constexpr int A_PLANE  = 32 * A_STRIDE;            // 4608
constexpr int B_BASE   = 2 * A_PLANE;              // 9216
constexpr int B_STRIDE = 528;                      // 256 px * 2B + 16 pad
constexpr int B_PLANE  = 32 * B_STRIDE;            // 16896
constexpr int STAGE_BYTES = B_BASE + 2 * B_PLANE;  // 43008
constexpr int D_STRIDE = 264;                      // f32, padded
constexpr int EPI_BYTES = 64 * D_STRIDE * 4;       // 67584
constexpr int DYN_BYTES = EPI_BYTES;               // > STAGE_BYTES

// ---------------- PTX wrappers (baseline ISA, verified in round 7) ---------
__device__ __forceinline__ void ldsm_x4t(uint32_t* f, uint32_t addr) {
    asm volatile("ldmatrix.sync.aligned.m8n8.x4.trans.shared.b16 "
                 "{%0,%1,%2,%3}, [%4];"
                 : "=r"(f[0]), "=r"(f[1]), "=r"(f[2]), "=r"(f[3]) : "r"(addr));
}
__device__ __forceinline__ void ldsm_x2t(uint32_t& f0, uint32_t& f1, uint32_t addr) {
    asm volatile("ldmatrix.sync.aligned.m8n8.x2.trans.shared.b16 "
                 "{%0,%1}, [%2];"
                 : "=r"(f0), "=r"(f1) : "r"(addr));
}
__device__ __forceinline__ void mma_bf16(float* d, const uint32_t* a,
                                         uint32_t b0, uint32_t b1) {
    asm volatile("mma.sync.aligned.m16n8k16.row.col.f32.bf16.bf16.f32 "
                 "{%0,%1,%2,%3}, {%4,%5,%6,%7}, {%8,%9}, {%0,%1,%2,%3};"
                 : "+f"(d[0]), "+f"(d[1]), "+f"(d[2]), "+f"(d[3])
                 : "r"(a[0]), "r"(a[1]), "r"(a[2]), "r"(a[3]), "r"(b0), "r"(b1));
}
__device__ __forceinline__ uint32_t cvt_bf16x2(float v1, float v0) {
    uint32_t r;
    asm("cvt.rn.bf16x2.f32 %0, %1, %2;" : "=r"(r) : "f"(v1), "f"(v0));
    return r;
}
__device__ __forceinline__ void split2(float v0, float v1,
                                       uint32_t& hi, uint32_t& lo) {
    hi = cvt_bf16x2(v1, v0);
    float h0 = __uint_as_float(hi << 16);
    float h1 = __uint_as_float(hi & 0xFFFF0000u);
    lo = cvt_bf16x2(v1 - h1, v0 - h0);
}

__global__ __launch_bounds__(256, 2)
void corr_mma8_kernel(const float* __restrict__ in1,
                      const float* __restrict__ in2,
                      float* __restrict__ out) {
    extern __shared__ char sm[];
    const uint32_t smb = (uint32_t)__cvta_generic_to_shared(sm);

    const int tid  = threadIdx.x;
    const int warp = tid >> 5;
    const int lane = tid & 31;
    const int b  = blockIdx.z;
    const int w0 = blockIdx.x * TW;
    const int h0 = blockIdx.y * TH;

    // ------------- conversion roles: lane-within-warp = channel -------------
    // (k = lane keeps STS phases conflict-free: bank = stride/16 * k mod 8)
    const int ck   = tid & 31;   // channel within chunk
    const int slot = tid >> 5;   // 0..7: A h-row; B row-pair
    const float4* ap = (const float4*)(in1 +
        ((size_t)(b * C + ck) * H + (h0 + slot)) * W + w0);
    const int gy0 = h0 + 2 * slot - PAD, gy1 = gy0 + 1;
    const bool vy0 = (gy0 >= 0 && gy0 < H);
    const bool vy1 = (gy1 >= 0 && gy1 < H);
    const float4* bp0 = (const float4*)(in2 +
        ((size_t)(b * C + ck) * H + (vy0 ? gy0 : 0)) * W + (w0 - PAD));
    const float4* bp1 = (const float4*)(in2 +
        ((size_t)(b * C + ck) * H + (vy1 ? gy1 : 0)) * W + (w0 - PAD));
    const bool g0ok = (w0 > 0), g3ok = (w0 < 120);
    const float4 zero4 = make_float4(0.f, 0.f, 0.f, 0.f);

    // ------------- MMA roles -------------------------------------------------
    const uint32_t a_row = (uint32_t)(((lane >> 4) << 3) + (lane & 7));
    const uint32_t a_px8 = (uint32_t)(((lane >> 3) & 1) << 3);
    const uint32_t b_row = (uint32_t)((((lane >> 3) & 1) << 3) + (lane & 7));
    const int q_base = warp * 32;     // warp owns halo cols q_base..q_base+31

    float acc[4][4][4];
#pragma unroll
    for (int mt = 0; mt < 4; ++mt)
#pragma unroll
        for (int nt = 0; nt < 4; ++nt)
#pragma unroll
            for (int q = 0; q < 4; ++q) acc[mt][nt][q] = 0.f;

#pragma unroll 1
    for (int k = 0; k < NCHUNK; ++k) {
        __syncthreads();   // previous chunk's MMA done reading the stage

        // --- load + convert + STS:  A tile (this thread: 8 px of row slot) ---
        {
            float4 va0 = __ldg(ap), va1 = __ldg(ap + 1);
            ap += CCH * HW / 4;
            uint32_t hi[4], lo[4];
            split2(va0.x, va0.y, hi[0], lo[0]);
            split2(va0.z, va0.w, hi[1], lo[1]);
            split2(va1.x, va1.y, hi[2], lo[2]);
            split2(va1.z, va1.w, hi[3], lo[3]);
            char* p = sm + ck * A_STRIDE + slot * 16;
            *(uint4*)(p)           = make_uint4(hi[0], hi[1], hi[2], hi[3]);
            *(uint4*)(p + A_PLANE) = make_uint4(lo[0], lo[1], lo[2], lo[3]);
        }
        // --- B halo rows 2*slot, 2*slot+1 (16 px each, zero-padded) ---------
#pragma unroll
        for (int rr = 0; rr < 2; ++rr) {
            const float4* bp = rr ? bp1 : bp0;
            const bool vy = rr ? vy1 : vy0;
            float4 v4[4];
            v4[0] = (vy && g0ok) ? __ldg(bp)     : zero4;
            v4[1] = vy           ? __ldg(bp + 1) : zero4;
            v4[2] = vy           ? __ldg(bp + 2) : zero4;
            v4[3] = (vy && g3ok) ? __ldg(bp + 3) : zero4;
            float v[16] = {v4[0].x, v4[0].y, v4[0].z, v4[0].w,
                           v4[1].x, v4[1].y, v4[1].z, v4[1].w,
                           v4[2].x, v4[2].y, v4[2].z, v4[2].w,
                           v4[3].x, v4[3].y, v4[3].z, v4[3].w};
            uint32_t hi[8], lo[8];
#pragma unroll
            for (int j = 0; j < 8; ++j) split2(v[2 * j], v[2 * j + 1], hi[j], lo[j]);
            char* p = sm + B_BASE + ck * B_STRIDE + (2 * slot + rr) * 32;
            *(uint4*)(p)                = make_uint4(hi[0], hi[1], hi[2], hi[3]);
            *(uint4*)(p + 16)           = make_uint4(hi[4], hi[5], hi[6], hi[7]);
            *(uint4*)(p + B_PLANE)      = make_uint4(lo[0], lo[1], lo[2], lo[3]);
            *(uint4*)(p + B_PLANE + 16) = make_uint4(lo[4], lo[5], lo[6], lo[7]);
        }
        bp0 += CCH * HW / 4;
        bp1 += CCH * HW / 4;

        __syncthreads();   // stage ready

        // --- MMA: 2 k16 steps, 4 mt x 4 nt, 3 split products -----------------
#pragma unroll
        for (int ks = 0; ks < 2; ++ks) {
            uint32_t Ah[4][4], Al[4][4];
#pragma unroll
            for (int mt = 0; mt < 4; ++mt) {
                uint32_t aaddr = smb + (ks * 16 + a_row) * A_STRIDE
                               + (uint32_t)(mt * 16) * 2 + a_px8 * 2;
                ldsm_x4t(Ah[mt], aaddr);
                ldsm_x4t(Al[mt], aaddr + A_PLANE);
            }
#pragma unroll
            for (int nt = 0; nt < 4; ++nt) {
                uint32_t baddr = smb + B_BASE + (ks * 16 + b_row) * B_STRIDE
                               + (uint32_t)(q_base + nt * 8) * 2;
                uint32_t bh0, bh1, bl0, bl1;
                ldsm_x2t(bh0, bh1, baddr);
                ldsm_x2t(bl0, bl1, baddr + B_PLANE);
#pragma unroll
                for (int mt = 0; mt < 4; ++mt) mma_bf16(acc[mt][nt], Ah[mt], bh0, bh1);
#pragma unroll
                for (int mt = 0; mt < 4; ++mt) mma_bf16(acc[mt][nt], Al[mt], bh0, bh1);
#pragma unroll
                for (int mt = 0; mt < 4; ++mt) mma_bf16(acc[mt][nt], Ah[mt], bl0, bl1);
            }
        }
    }

    // ---------------- epilogue: acc -> smem D -> banded coalesced stores ----
    __syncthreads();            // all MMA smem reads done; stage is dead
    float* D = (float*)sm;      // [px 0..63][q 0..255] stride 264

    {
        const int r  = lane >> 2;
        const int c2 = (lane & 3) * 2;
#pragma unroll
        for (int mt = 0; mt < 4; ++mt)
#pragma unroll
            for (int nt = 0; nt < 4; ++nt) {
                const float* d = acc[mt][nt];
                const int px = mt * 16 + r;
                const int q  = q_base + nt * 8 + c2;
                *(float2*)&D[px * D_STRIDE + q]       = make_float2(d[0], d[1]);
                *(float2*)&D[(px + 8) * D_STRIDE + q] = make_float2(d[2], d[3]);
            }
    }
    __syncthreads();

    // 648 output rows (81 planes x 8 h-rows) of 8 floats, coalesced float4 x2
    for (int i = tid; i < TH * PATCH * PATCH; i += 256) {
        const int hp = i & 7, dd = i >> 3;      // dd = dy*9+dx
        const int dy = dd / 9, dx = dd % 9;
        float v[8];
#pragma unroll
        for (int wp = 0; wp < 8; ++wp)
            v[wp] = D[(hp * 8 + wp) * D_STRIDE + (hp + dy) * 16 + wp + dx];
        float* op = out + (((size_t)b * (PATCH * PATCH) + dd) * H + (h0 + hp)) * W + w0;
        *(float4*)(op)     = make_float4(v[0], v[1], v[2], v[3]);
        *(float4*)(op + 4) = make_float4(v[4], v[5], v[6], v[7]);
    }
}

}  // namespace

extern "C" void kernel_launch(void* const* d_in, const int* in_sizes, int n_in,
                              void* d_out, int out_size) {
    const float* in1 = (const float*)d_in[0];
    const float* in2 = (const float*)d_in[1];
    float* out = (float*)d_out;

    cudaFuncSetAttribute(corr_mma8_kernel,
                         cudaFuncAttributeMaxDynamicSharedMemorySize,
                         DYN_BYTES);

    int B = in_sizes[0] / (C * H * W);              // 4
    dim3 grid(W / TW, H / TH, B);                   // (16, 16, 4) = 1024
    corr_mma8_kernel<<<grid, 256, DYN_BYTES>>>(in1, in2, out);
}

// round 9
// speedup vs baseline: 1.6458x; 1.6458x over previous
#include <cuda_runtime.h>
#include <cstdint>

// SpatialCorrelationSampler via warp-level mma.sync tf32 (single product).
// out[b, dy*9+dx, h, w] = sum_c in1[b,c,h,w] * in2_zp4[b,c,h+dy,w+dx]
// in1,in2: (4,256,128,128) fp32; out: (4,81,128,128) fp32.
//
// Per block: tile 8x8 px (M=64), halo 16x16 (N=256), K=256.
// cp.async streams RAW fp32 (2-stage ring); cvt.rna.tf32 applied on
// fragment registers. MMA m16n8k8 tf32, fp32 accum. Banded epilogue.

namespace {

constexpr int C = 256, H = 128, W = 128, PATCH = 9, PAD = 4;
constexpr int HW = H * W;
constexpr int TW = 8, TH = 8;
constexpr int CCH = 32, NCHUNK = C / CCH;         // 8
constexpr int CHBYTES = CCH * HW * 4;             // 2 MB per chunk

// fp32 stage layouts, [k][p] / [k][q], strides mod 128B == 32 (conflict-free)
constexpr int A_ST = 72;                          // floats (64 + 8 pad)
constexpr int B_ST = 264;                         // floats (256 + 8 pad)
constexpr int A_STAGE = CCH * A_ST * 4;           // 9216
constexpr int B_STAGE = CCH * B_ST * 4;           // 33792
constexpr int STAGE  = A_STAGE + B_STAGE;         // 43008
constexpr int DYN_BYTES = 2 * STAGE;              // 86016 (epi 67584 fits)
constexpr int D_STRIDE = 264;

// ---------------- PTX wrappers (baseline ISA) ------------------------------
__device__ __forceinline__ void cp16(uint32_t dst, const void* src, uint32_t sz) {
    asm volatile("cp.async.cg.shared.global [%0], [%1], 16, %2;"
                 :: "r"(dst), "l"(src), "r"(sz));
}
__device__ __forceinline__ void cp_commit() {
    asm volatile("cp.async.commit_group;" ::: "memory");
}
__device__ __forceinline__ void cp_wait0() {
    asm volatile("cp.async.wait_group 0;" ::: "memory");
}
__device__ __forceinline__ uint32_t to_tf32(float f) {
    uint32_t u;
    asm("cvt.rna.tf32.f32 %0, %1;" : "=r"(u) : "f"(f));
    return u;
}
__device__ __forceinline__ void mma_tf32(float* d, const uint32_t* a,
                                         uint32_t b0, uint32_t b1) {
    asm volatile("mma.sync.aligned.m16n8k8.row.col.f32.tf32.tf32.f32 "
                 "{%0,%1,%2,%3}, {%4,%5,%6,%7}, {%8,%9}, {%0,%1,%2,%3};"
                 : "+f"(d[0]), "+f"(d[1]), "+f"(d[2]), "+f"(d[3])
                 : "r"(a[0]), "r"(a[1]), "r"(a[2]), "r"(a[3]), "r"(b0), "r"(b1));
}

__global__ __launch_bounds__(256, 2)
void corr_tf32_kernel(const float* __restrict__ in1,
                      const float* __restrict__ in2,
                      float* __restrict__ out) {
    extern __shared__ char sm[];
    const uint32_t smb = (uint32_t)__cvta_generic_to_shared(sm);

    const int tid  = threadIdx.x;
    const int warp = tid >> 5;
    const int lane = tid & 31;
    const int b  = blockIdx.z;
    const int w0 = blockIdx.x * TW;
    const int h0 = blockIdx.y * TH;

    // ------------- cp.async slot precompute (10 x 16B per thread) ----------
    // slots 0..511: A tile  [k(32)][p(64)];  512..2559: B halo [k(32)][q(256)]
    uint32_t smoff[10], gb[10], sz[10];
#pragma unroll
    for (int i = 0; i < 10; ++i) {
        int s = tid + i * 256;
        if (s < 512) {                       // A (i = 0,1)
            int kk = s >> 4, j = s & 15;     // j*4 .. j*4+4 = p range
            int py = j >> 1, px = (j & 1) * 4;
            smoff[i] = (uint32_t)((kk * A_ST + j * 4) * 4);
            gb[i] = (uint32_t)((((b * C + kk) * H + h0 + py) * W + w0 + px) * 4);
            sz[i] = 16;
        } else {                              // B (i = 2..9)
            int u = s - 512;
            int kk = u >> 6, j = u & 63;
            int hy = j >> 2;
            int gy = h0 + hy - PAD;
            int gx = w0 + (j & 3) * 4 - PAD;  // 16B aligned, all-in or all-out
            bool ok = (gy >= 0 && gy < H && gx >= 0 && gx + 4 <= W);
            smoff[i] = (uint32_t)(A_STAGE + (kk * B_ST + j * 4) * 4);
            gb[i] = ok ? (uint32_t)((((b * C + kk) * H + gy) * W + gx) * 4) : 0u;
            sz[i] = ok ? 16u : 0u;
        }
    }

    auto issue = [&](int ch) {
        uint32_t sbase = smb + (uint32_t)((ch & 1) * STAGE);
        size_t coff = (size_t)ch * CHBYTES;
#pragma unroll
        for (int i = 0; i < 10; ++i) {
            const char* base = (i < 2) ? (const char*)in1 : (const char*)in2;
            cp16(sbase + smoff[i], base + coff + gb[i], sz[i]);
        }
        cp_commit();
    };

    issue(0);

    // ------------- MMA roles -------------------------------------------------
    const int g = lane >> 2, t = lane & 3;
    const int q_base = warp * 32;            // warp owns halo cols [q_base, +32)

    float acc[4][4][4];
#pragma unroll
    for (int mt = 0; mt < 4; ++mt)
#pragma unroll
        for (int nt = 0; nt < 4; ++nt)
#pragma unroll
            for (int q = 0; q < 4; ++q) acc[mt][nt][q] = 0.f;

#pragma unroll 1
    for (int k = 0; k < NCHUNK; ++k) {
        cp_wait0();        // chunk k's copies landed (only pending group)
        __syncthreads();   // data visible to all; all done reading stage (k+1)&1

        if (k + 1 < NCHUNK) issue(k + 1);

        const float* A  = (const float*)(sm + (k & 1) * STAGE);
        const float* Bs = (const float*)(sm + (k & 1) * STAGE + A_STAGE);

#pragma unroll
        for (int ks = 0; ks < 4; ++ks) {     // 4 k8-steps per 32-channel chunk
            const int arow = (ks * 8 + t) * A_ST + g;
            uint32_t af[4][4];
#pragma unroll
            for (int mt = 0; mt < 4; ++mt) {
                const float* p = A + arow + mt * 16;
                af[mt][0] = to_tf32(p[0]);            // (p=g,    k=t)
                af[mt][1] = to_tf32(p[8]);            // (p=g+8,  k=t)
                af[mt][2] = to_tf32(p[4 * A_ST]);     // (p=g,    k=t+4)
                af[mt][3] = to_tf32(p[4 * A_ST + 8]); // (p=g+8,  k=t+4)
            }
            const int brow = (ks * 8 + t) * B_ST + q_base + g;
#pragma unroll
            for (int nt = 0; nt < 4; ++nt) {
                uint32_t b0 = to_tf32(Bs[brow + nt * 8]);            // (k=t,   q)
                uint32_t b1 = to_tf32(Bs[brow + nt * 8 + 4 * B_ST]); // (k=t+4, q)
#pragma unroll
                for (int mt = 0; mt < 4; ++mt)
                    mma_tf32(acc[mt][nt], af[mt], b0, b1);
            }
        }
    }

    // ---------------- epilogue: acc -> smem D -> banded coalesced stores ----
    __syncthreads();            // all MMA smem reads done; stages are dead
    float* D = (float*)sm;      // [px 0..63][q 0..255] stride 264 (67.6 KB)

    {
        const int c2 = t * 2;
#pragma unroll
        for (int mt = 0; mt < 4; ++mt)
#pragma unroll
            for (int nt = 0; nt < 4; ++nt) {
                const float* d = acc[mt][nt];
                const int px = mt * 16 + g;
                const int q  = q_base + nt * 8 + c2;
                *(float2*)&D[px * D_STRIDE + q]       = make_float2(d[0], d[1]);
                *(float2*)&D[(px + 8) * D_STRIDE + q] = make_float2(d[2], d[3]);
            }
    }
    __syncthreads();

    // 648 output rows (81 planes x 8 h-rows) of 8 floats, coalesced
    for (int i = tid; i < TH * PATCH * PATCH; i += 256) {
        const int hp = i & 7, dd = i >> 3;    // dd = dy*9+dx
        const int dy = dd / 9, dx = dd % 9;
        float v[8];
#pragma unroll
        for (int wp = 0; wp < 8; ++wp)
            v[wp] = D[(hp * 8 + wp) * D_STRIDE + (hp + dy) * 16 + wp + dx];
        float* op = out + (((size_t)b * (PATCH * PATCH) + dd) * H + (h0 + hp)) * W + w0;
        *(float4*)(op)     = make_float4(v[0], v[1], v[2], v[3]);
        *(float4*)(op + 4) = make_float4(v[4], v[5], v[6], v[7]);
    }
}

}  // namespace

extern "C" void kernel_launch(void* const* d_in, const int* in_sizes, int n_in,
                              void* d_out, int out_size) {
    const float* in1 = (const float*)d_in[0];
    const float* in2 = (const float*)d_in[1];
    float* out = (float*)d_out;

    cudaFuncSetAttribute(corr_tf32_kernel,
                         cudaFuncAttributeMaxDynamicSharedMemorySize,
                         DYN_BYTES);

    int B = in_sizes[0] / (C * H * W);              // 4
    dim3 grid(W / TW, H / TH, B);                   // (16, 16, 4) = 1024
    corr_tf32_kernel<<<grid, 256, DYN_BYTES>>>(in1, in2, out);
}

// round 11
// speedup vs baseline: 1.9220x; 1.1678x over previous
#include <cuda_runtime.h>
#include <cstdint>

// SpatialCorrelationSampler via warp-level mma.sync tf32 (single product).
// Round 11: round-10 structure (band-skip GEMM: warp = (m16 tile, q-half),
// only the 10 needed halo rows per tile -> 37.5% fewer MMAs; 4-stage
// cp.async ring, CCH=16, issued 3 ahead) with the D_STRIDE alignment fix
// (264, even -> float2 epilogue stores stay 8B-aligned).
//
// Per block: tile 8x8 px (M=64), halo 16x16 (N=256), K=256.

namespace {

constexpr int C = 256, H = 128, W = 128, PATCH = 9, PAD = 4;
constexpr int HW = H * W;
constexpr int TW = 8, TH = 8;
constexpr int CCH = 16, NCHUNK = C / CCH;         // 16
constexpr int CHBYTES = CCH * HW * 4;

// fp32 stage layouts, [k][p] / [k][q], strides mod 32 words == 8 (confl-free)
constexpr int A_ST = 72;                          // floats
constexpr int B_ST = 264;                         // floats
constexpr int A_STAGE = CCH * A_ST * 4;           // 4608
constexpr int B_STAGE = CCH * B_ST * 4;           // 16896
constexpr int STAGE  = A_STAGE + B_STAGE;         // 21504
constexpr int STAGES = 4;
constexpr int D_STRIDE = 264;                     // EVEN: float2 stores aligned
constexpr int EPI_BYTES = 64 * D_STRIDE * 4;      // 67584
constexpr int DYN_BYTES = STAGES * STAGE;         // 86016 > EPI_BYTES

constexpr int SLOTS = 5;    // (256 + 1024) float4 per chunk / 256 threads

// ---------------- PTX wrappers (baseline ISA) ------------------------------
__device__ __forceinline__ void cp16(uint32_t dst, const void* src, uint32_t sz) {
    asm volatile("cp.async.cg.shared.global [%0], [%1], 16, %2;"
                 :: "r"(dst), "l"(src), "r"(sz));
}
__device__ __forceinline__ void cp_commit() {
    asm volatile("cp.async.commit_group;" ::: "memory");
}
__device__ __forceinline__ void cp_wait2() {
    asm volatile("cp.async.wait_group 2;" ::: "memory");
}
__device__ __forceinline__ uint32_t to_tf32(float f) {
    uint32_t u;
    asm("cvt.rna.tf32.f32 %0, %1;" : "=r"(u) : "f"(f));
    return u;
}
__device__ __forceinline__ void mma_tf32(float* d, const uint32_t* a,
                                         uint32_t b0, uint32_t b1) {
    asm volatile("mma.sync.aligned.m16n8k8.row.col.f32.tf32.tf32.f32 "
                 "{%0,%1,%2,%3}, {%4,%5,%6,%7}, {%8,%9}, {%0,%1,%2,%3};"
                 : "+f"(d[0]), "+f"(d[1]), "+f"(d[2]), "+f"(d[3])
                 : "r"(a[0]), "r"(a[1]), "r"(a[2]), "r"(a[3]), "r"(b0), "r"(b1));
}

__global__ __launch_bounds__(256, 2)
void corr_tf32b_kernel(const float* __restrict__ in1,
                       const float* __restrict__ in2,
                       float* __restrict__ out) {
    extern __shared__ char sm[];
    const uint32_t smb = (uint32_t)__cvta_generic_to_shared(sm);

    const int tid  = threadIdx.x;
    const int warp = tid >> 5;
    const int lane = tid & 31;
    const int b  = blockIdx.z;
    const int w0 = blockIdx.x * TW;
    const int h0 = blockIdx.y * TH;

    // ------------- cp.async slot precompute (5 x 16B per thread) -----------
    // slots 0..255: A [k(16)][p(64)];  256..1279: B [k(16)][q(256)]
    uint32_t smoff[SLOTS], gb[SLOTS], sz[SLOTS];
#pragma unroll
    for (int i = 0; i < SLOTS; ++i) {
        int s = tid + i * 256;
        if (s < 256) {                        // A (i = 0)
            int kk = s >> 4, j = s & 15;
            int py = j >> 1, px = (j & 1) * 4;
            smoff[i] = (uint32_t)((kk * A_ST + j * 4) * 4);
            gb[i] = (uint32_t)((((b * C + kk) * H + h0 + py) * W + w0 + px) * 4);
            sz[i] = 16;
        } else {                              // B (i = 1..4)
            int u = s - 256;
            int kk = u >> 6, j = u & 63;
            int hy = j >> 2;
            int gy = h0 + hy - PAD;
            int gx = w0 + (j & 3) * 4 - PAD;  // 16B aligned, all-in or all-out
            bool ok = (gy >= 0 && gy < H && gx >= 0 && gx + 4 <= W);
            smoff[i] = (uint32_t)(A_STAGE + (kk * B_ST + j * 4) * 4);
            gb[i] = ok ? (uint32_t)((((b * C + kk) * H + gy) * W + gx) * 4) : 0u;
            sz[i] = ok ? 16u : 0u;
        }
    }

    auto issue = [&](int ch) {
        if (ch < NCHUNK) {
            uint32_t sbase = smb + (uint32_t)((ch & 3) * STAGE);
            size_t coff = (size_t)ch * CHBYTES;
#pragma unroll
            for (int i = 0; i < SLOTS; ++i) {
                const char* base = (i == 0) ? (const char*)in1 : (const char*)in2;
                cp16(sbase + smoff[i], base + coff + gb[i], sz[i]);
            }
        }
        cp_commit();   // uniform group accounting (empty groups at the tail)
    };

    issue(0); issue(1); issue(2);

    // ------------- MMA roles: warp = (mt, half) ----------------------------
    const int g = lane >> 2, t = lane & 3;
    const int mt   = warp >> 1;            // m16 tile: px [mt*16, +16)
    const int half = warp & 1;
    const int qr0  = 2 * mt + 5 * half;    // first of 5 owned halo rows

    float acc[10][4];                      // j = (row 0..4)*2 + (n8 col 0..1)
#pragma unroll
    for (int j = 0; j < 10; ++j)
#pragma unroll
        for (int q = 0; q < 4; ++q) acc[j][q] = 0.f;

#pragma unroll 1
    for (int k = 0; k < NCHUNK; ++k) {
        cp_wait2();        // exactly 3 groups pending -> group k complete
        __syncthreads();   // stage k visible; stage (k+3)&3 fully read (iter k-1)

        issue(k + 3);

        const float* A  = (const float*)(sm + (k & 3) * STAGE);
        const float* Bs = A + A_STAGE / 4;

#pragma unroll
        for (int ks = 0; ks < 2; ++ks) {   // 2 k8-steps per 16-channel chunk
            const float* ap = A + (ks * 8 + t) * A_ST + mt * 16 + g;
            uint32_t af[4];
            af[0] = to_tf32(ap[0]);
            af[1] = to_tf32(ap[8]);
            af[2] = to_tf32(ap[4 * A_ST]);
            af[3] = to_tf32(ap[4 * A_ST + 8]);

            const float* bp = Bs + (ks * 8 + t) * B_ST + g;
#pragma unroll
            for (int j = 0; j < 10; ++j) {
                const int q = (qr0 + (j >> 1)) * 16 + (j & 1) * 8;
                uint32_t b0 = to_tf32(bp[q]);
                uint32_t b1 = to_tf32(bp[q + 4 * B_ST]);
                mma_tf32(acc[j], af, b0, b1);
            }
        }
    }

    // ---------------- epilogue: acc -> smem D (banded) -> coalesced stores --
    __syncthreads();            // all MMA smem reads done; stages are dead
    float* D = (float*)sm;      // [px 0..63][q 0..255] stride 264

    {
        const int c2 = t * 2;
#pragma unroll
        for (int j = 0; j < 10; ++j) {
            const int q = (qr0 + (j >> 1)) * 16 + (j & 1) * 8 + c2;
            const int px = mt * 16 + g;
            *(float2*)&D[px * D_STRIDE + q]       = make_float2(acc[j][0], acc[j][1]);
            *(float2*)&D[(px + 8) * D_STRIDE + q] = make_float2(acc[j][2], acc[j][3]);
        }
    }
    __syncthreads();

    // 648 output rows (81 planes x 8 h-rows) of 8 floats, coalesced
    for (int i = tid; i < TH * PATCH * PATCH; i += 256) {
        const int hp = i & 7, dd = i >> 3;    // dd = dy*9+dx
        const int dy = dd / 9, dx = dd % 9;
        float v[8];
#pragma unroll
        for (int wp = 0; wp < 8; ++wp)
            v[wp] = D[(hp * 8 + wp) * D_STRIDE + (hp + dy) * 16 + wp + dx];
        float* op = out + (((size_t)b * (PATCH * PATCH) + dd) * H + (h0 + hp)) * W + w0;
        *(float4*)(op)     = make_float4(v[0], v[1], v[2], v[3]);
        *(float4*)(op + 4) = make_float4(v[4], v[5], v[6], v[7]);
    }
}

}  // namespace

extern "C" void kernel_launch(void* const* d_in, const int* in_sizes, int n_in,
                              void* d_out, int out_size) {
    const float* in1 = (const float*)d_in[0];
    const float* in2 = (const float*)d_in[1];
    float* out = (float*)d_out;

    cudaFuncSetAttribute(corr_tf32b_kernel,
                         cudaFuncAttributeMaxDynamicSharedMemorySize,
                         DYN_BYTES);

    int B = in_sizes[0] / (C * H * W);              // 4
    dim3 grid(W / TW, H / TH, B);                   // (16, 16, 4) = 1024
    corr_tf32b_kernel<<<grid, 256, DYN_BYTES>>>(in1, in2, out);
}